// round 13
// baseline (speedup 1.0000x reference)
#include <cuda_runtime.h>
#include <cuda_fp16.h>
#include <cstdint>

// ---------------- problem constants ----------------
#define HW    50176          // 224*224 (= 1024 windows * 49)
#define NTILE 392            // HW / 128

// scratch  (qkv padded by 64 halves for attention's aligned-span loads)
__device__ __half g_qkvh[77070400];  // [4][384][p' window-major] fp16
__device__ __half g_xh[25690112];    // x tiles [4*392][n=128 (p')][k=128] fp16
__device__ __half g_wh[65536];       // w_qkv (384 rows) then w_out (128 rows), [row][128]

// ---------------- helpers ----------------
__device__ __forceinline__ uint32_t smem_u32(const void* p){
    uint32_t a;
    asm("{ .reg .u64 t; cvta.to.shared.u64 t, %1; cvt.u32.u64 %0, t; }" : "=r"(a) : "l"(p));
    return a;
}
__device__ __forceinline__ uint32_t pack_h2(float a, float b){
    __half2 h = __floats2half2_rn(a, b);
    return *(uint32_t*)&h;
}

#define LDSM_X4(r0, r1, r2, r3, addr)                                                     \
    asm volatile("ldmatrix.sync.aligned.m8n8.x4.shared.b16 {%0,%1,%2,%3}, [%4];"          \
        : "=r"(r0), "=r"(r1), "=r"(r2), "=r"(r3) : "r"(addr))

#define LDSM_X4T(r0, r1, r2, r3, addr)                                                    \
    asm volatile("ldmatrix.sync.aligned.m8n8.x4.trans.shared.b16 {%0,%1,%2,%3}, [%4];"    \
        : "=r"(r0), "=r"(r1), "=r"(r2), "=r"(r3) : "r"(addr))

#define MMA_F16(d, a, b0, b1)                                                             \
    asm volatile("mma.sync.aligned.m16n8k16.row.col.f32.f16.f16.f32 "                     \
        "{%0,%1,%2,%3}, {%4,%5,%6,%7}, {%8,%9}, {%0,%1,%2,%3};"                           \
        : "+f"((d)[0]), "+f"((d)[1]), "+f"((d)[2]), "+f"((d)[3])                          \
        : "r"((a)[0]), "r"((a)[1]), "r"((a)[2]), "r"((a)[3]), "r"(b0), "r"(b1))

#define CP16(dst, src)                                                                    \
    asm volatile("cp.async.ca.shared.global [%0], [%1], 16;" :: "r"(dst), "l"(src) : "memory")
#define CP_COMMIT  asm volatile("cp.async.commit_group;" ::: "memory")
#define CP_WAIT(n) asm volatile("cp.async.wait_group %0;" :: "n"(n) : "memory")

// =====================================================================
// weight fp32 -> fp16 (one-shot, tiny)
// =====================================================================
__global__ void wconv(const float* __restrict__ W, __half* __restrict__ Wh, int n4)
{
    int i = blockIdx.x * 256 + threadIdx.x;
    if (i >= n4) return;
    float4 v = ((const float4*)W)[i];
    *(uint2*)(Wh + i*4) = make_uint2(pack_h2(v.x, v.y), pack_h2(v.z, v.w));
}

// =====================================================================
// xconv: band-wise coalesced transpose (unchanged, proven).
// =====================================================================
#define XC_PITCH 1632
#define XCONV_SMEM (16*XC_PITCH*4)   // 104448
__global__ __launch_bounds__(256)
void xconv(const float* __restrict__ X, __half* __restrict__ Xh)
{
    extern __shared__ float ts[];
    const int tid  = threadIdx.x;
    const int band = blockIdx.x;
    const int half = blockIdx.y;
    const int b    = blockIdx.z;
    const int ch0  = half * 64;

    #pragma unroll 1
    for (int g = 0; g < 4; g++){
        if (g) __syncthreads();
        const int cbase = ch0 + g * 16;

        #pragma unroll
        for (int i = 0; i < 25; i++){
            int idx = tid + i * 256;
            if (idx < 6272){
                int c = idx / 392;
                int j = idx - c * 392;
                float4 v = *(const float4*)(X + ((size_t)(b*128 + cbase + c)) * HW + band*1568 + j*4);
                int r = j / 56;
                float* d = ts + c * XC_PITCH + j*4 + r*8;
                d[0] = v.x; d[1] = v.y; d[2] = v.z; d[3] = v.w;
            }
        }
        __syncthreads();

        for (int idx = tid; idx < 1568; idx += 256){
            int lw = idx / 49;
            int l  = idx - lw * 49;
            int r  = l / 7;
            int q  = l - r * 7;
            int pb = r*224 + lw*7 + q + r*8;
            uint32_t h[8];
            #pragma unroll
            for (int j = 0; j < 8; j++){
                float v0 = ts[(2*j  ) * XC_PITCH + pb];
                float v1 = ts[(2*j+1) * XC_PITCH + pb];
                h[j] = pack_h2(v0, v1);
            }
            int pg = (band*32 + lw) * 49 + l;
            int t = pg >> 7, n = pg & 127;
            __half* o = Xh + (((size_t)(b*NTILE + t)) * 128 + n) * 128 + cbase;
            *(uint4*)(o)     = make_uint4(h[0], h[1], h[2], h[3]);
            *(uint4*)(o + 8) = make_uint4(h[4], h[5], h[6], h[7]);
        }
    }
}

// =====================================================================
// fp16 mma.sync GEMM with cp.async 2-chunk pipeline (QKV only now).
// =====================================================================
#define CPITCH 144
#define STG_B  18432
#define STGSZ  36864
#define GEMM_SMEM (2*STGSZ)        // 73728

__global__ __launch_bounds__(256, 2)
void gemm_tc(const __half* __restrict__ Wh, int wofs,
             const __half* __restrict__ Bt,
             const float* __restrict__ bias, __half* __restrict__ OutH,
             int Mtot)
{
    extern __shared__ char sm[];
    const uint32_t sb = smem_u32(sm);
    const int tid  = threadIdx.x;
    const int wid  = tid >> 5;
    const int lane = tid & 31;
    const int nt_blk = blockIdx.x;
    const int m0t    = blockIdx.y * 128;
    const int b      = blockIdx.z;

    const __half* wp = Wh + wofs + (size_t)m0t * 128;
    const __half* bp = Bt + (((size_t)(b * NTILE + nt_blk)) << 14);

    #pragma unroll
    for (int ch = 0; ch < 2; ch++){
        uint32_t s0 = sb + ch * STGSZ;
        #pragma unroll
        for (int i = 0; i < 4; i++){
            int idx = tid + i * 256;
            int row = idx >> 3, piece = idx & 7;
            CP16(s0 + row * CPITCH + piece * 16, wp + row * 128 + ch * 64 + piece * 8);
        }
        #pragma unroll
        for (int i = 0; i < 4; i++){
            int idx = tid + i * 256;
            int row = idx >> 3, piece = idx & 7;
            CP16(s0 + STG_B + row * CPITCH + piece * 16, bp + row * 128 + ch * 64 + piece * 8);
        }
        CP_COMMIT;
    }

    const int m0w = (wid >> 1) * 32;
    const int n0w = (wid & 1) * 64;
    const int row8 = lane & 7, quad = lane >> 3;

    uint32_t aoff[2], boff[2];
    #pragma unroll
    for (int mt = 0; mt < 2; mt++)
        aoff[mt] = (uint32_t)((m0w + mt*16 + ((quad & 1) << 3) + row8) * CPITCH + ((quad >> 1) << 4));
    #pragma unroll
    for (int g = 0; g < 2; g++)
        boff[g] = (uint32_t)(STG_B + (n0w + g*32 + (quad << 3) + row8) * CPITCH);

    float acc[2][8][4];
    #pragma unroll
    for (int mt = 0; mt < 2; mt++)
        #pragma unroll
        for (int nt = 0; nt < 8; nt++)
            #pragma unroll
            for (int q = 0; q < 4; q++) acc[mt][nt][q] = 0.f;

    #pragma unroll
    for (int ch = 0; ch < 2; ch++){
        if (ch == 0) { CP_WAIT(1); } else { CP_WAIT(0); }
        __syncthreads();
        const uint32_t s0 = sb + ch * STGSZ;
        #pragma unroll
        for (int ks = 0; ks < 4; ks++){
            const uint32_t kb = ks * 32;
            uint32_t af[2][4], bf[2][2][4];
            #pragma unroll
            for (int mt = 0; mt < 2; mt++)
                LDSM_X4(af[mt][0], af[mt][1], af[mt][2], af[mt][3], s0 + aoff[mt] + kb);
            #pragma unroll
            for (int g = 0; g < 2; g++){
                LDSM_X4(bf[g][0][0], bf[g][0][1], bf[g][0][2], bf[g][0][3], s0 + boff[g] + kb);
                LDSM_X4(bf[g][1][0], bf[g][1][1], bf[g][1][2], bf[g][1][3], s0 + boff[g] + kb + 16);
            }
            #pragma unroll
            for (int mt = 0; mt < 2; mt++)
                #pragma unroll
                for (int nt = 0; nt < 8; nt++){
                    int g = nt >> 2, j = nt & 3;
                    MMA_F16(acc[mt][nt], af[mt], bf[g][0][j], bf[g][1][j]);
                }
        }
    }

    const int n0t = nt_blk * 128;
    #pragma unroll
    for (int mt = 0; mt < 2; mt++){
        int r0 = m0w + mt*16 + (lane >> 2);
        float bv0 = bias[m0t + r0];
        float bv1 = bias[m0t + r0 + 8];
        #pragma unroll
        for (int nt = 0; nt < 8; nt++){
            int col = n0t + n0w + nt*8 + ((lane & 3) << 1);
            *(uint32_t*)(OutH + ((size_t)(b * Mtot + m0t + r0)    ) * HW + col) =
                pack_h2(acc[mt][nt][0] + bv0, acc[mt][nt][1] + bv0);
            *(uint32_t*)(OutH + ((size_t)(b * Mtot + m0t + r0 + 8)) * HW + col) =
                pack_h2(acc[mt][nt][2] + bv1, acc[mt][nt][3] + bv1);
        }
    }
}

// =====================================================================
// FUSED attention + output projection. One CTA (256 thr) per window.
// Attention: warp = head (unchanged). Then k/v smem is reloaded with
// W_out and the proj GEMM runs in-CTA; final fp32 stored directly.
// =====================================================================
#define PH 136                       // [pos][c] pitch in halves (272B)
#define ATT_SMEM (3*64*PH*2 + 512)   // q/k/v + bias floats = 52736

__global__ __launch_bounds__(256, 2)
void attn_proj(const __half* __restrict__ qkv, const __half* __restrict__ Wout,
               const float* __restrict__ bias, float* __restrict__ Out)
{
    extern __shared__ __half asm_[];
    __half* qsm = asm_;                // [pos 64][128 c]; reused as O-stage
    __half* ksm = asm_ + 64*PH;        // K; later rows 0..63  of W_out
    __half* vsm = asm_ + 128*PH;       // V; later rows 64..127 of W_out
    float*  bsm = (float*)(asm_ + 192*PH);

    const int tid  = threadIdx.x;
    const int lane = tid & 31;
    const int wrp  = tid >> 5;         // head (attention phase)
    const int wi   = blockIdx.x;
    const int b    = wi >> 10;
    const int w    = wi & 1023;
    const int prow = (w >> 5) * 7, pcol = (w & 31) * 7;

    // zero pad rows 49..63 of q/k/v
    if (tid < 255){
        ((uint4*)(qsm + 49*PH))[tid] = make_uint4(0,0,0,0);
        ((uint4*)(ksm + 49*PH))[tid] = make_uint4(0,0,0,0);
        ((uint4*)(vsm + 49*PH))[tid] = make_uint4(0,0,0,0);
    }
    if (tid < 128) bsm[tid] = bias[tid];

    // ---- vectorized loads (aligned 64-half span per channel) ----
    const int w49    = w * 49;
    const int astart = w49 & ~7;
    const int off0   = astart - w49;
    const __half* qp = qkv + (size_t)(b * 384      ) * HW;
    const __half* kp = qkv + (size_t)(b * 384 + 128) * HW;
    const __half* vp = qkv + (size_t)(b * 384 + 256) * HW;
    const __half hscale = __float2half(0.25f);

    #pragma unroll
    for (int i = 0; i < 4; i++){
        int idx = tid + i * 256;
        int c = idx >> 3, piece = idx & 7;
        int p0 = off0 + piece * 8;
        size_t ga = (size_t)c * HW + astart + piece * 8;

        uint4 vq = *(const uint4*)(qp + ga);
        __half* hq = (__half*)&vq;
        #pragma unroll
        for (int j = 0; j < 8; j++){
            int p = p0 + j;
            if ((unsigned)p < 49u) qsm[p*PH + c] = __hmul(hq[j], hscale);
        }
        uint4 vk = *(const uint4*)(kp + ga);
        __half* hk = (__half*)&vk;
        #pragma unroll
        for (int j = 0; j < 8; j++){
            int p = p0 + j;
            if ((unsigned)p < 49u) ksm[p*PH + c] = hk[j];
        }
        uint4 vv = *(const uint4*)(vp + ga);
        __half* hv = (__half*)&vv;
        #pragma unroll
        for (int j = 0; j < 8; j++){
            int p = p0 + j;
            if ((unsigned)p < 49u) vsm[p*PH + c] = hv[j];
        }
    }
    __syncthreads();

    const uint32_t qsb = smem_u32(qsm), ksb = smem_u32(ksm), vsb = smem_u32(vsm);
    const int row8 = lane & 7, quad = lane >> 3;
    const int cbase = 2 * (lane & 3);
    const uint32_t hoff = (uint32_t)wrp * 32;

    uint32_t kf[2][2][4];
    #pragma unroll
    for (int g = 0; g < 2; g++){
        uint32_t ba = ksb + (uint32_t)((g*32 + quad*8 + row8) * (PH*2)) + hoff;
        LDSM_X4(kf[g][0][0], kf[g][0][1], kf[g][0][2], kf[g][0][3], ba);
        LDSM_X4(kf[g][1][0], kf[g][1][1], kf[g][1][2], kf[g][1][3], ba + 16);
    }
    uint32_t vf[4][4];
    #pragma unroll
    for (int ksp = 0; ksp < 4; ksp++){
        uint32_t va = vsb + (uint32_t)((ksp*16 + (lane & 15)) * (PH*2)) + hoff + ((lane >> 4) << 4);
        LDSM_X4T(vf[ksp][0], vf[ksp][1], vf[ksp][2], vf[ksp][3], va);
    }

    __half* ost = qsm;   // O stage: [pos][128c], warp-private col slice

    #pragma unroll
    for (int lt = 0; lt < 4; lt++){
        const int l0 = lt * 16;
        uint32_t af[4];
        LDSM_X4(af[0], af[1], af[2], af[3],
                qsb + (uint32_t)((l0 + ((quad & 1) << 3) + row8) * (PH*2)) + hoff + ((quad >> 1) << 4));

        float sc[8][4];
        #pragma unroll
        for (int nt = 0; nt < 8; nt++){
            sc[nt][0] = sc[nt][1] = sc[nt][2] = sc[nt][3] = 0.f;
            int g = nt >> 2, j = nt & 3;
            MMA_F16(sc[nt], af, kf[g][0][j], kf[g][1][j]);
        }

        float mx0 = -1e30f, mx1 = -1e30f;
        #pragma unroll
        for (int nt = 0; nt < 8; nt++){
            int col0 = nt*8 + cbase;
            if (col0 > 48){ sc[nt][0] = -1e30f; sc[nt][2] = -1e30f; }
            if (col0 + 1 > 48){ sc[nt][1] = -1e30f; sc[nt][3] = -1e30f; }
            mx0 = fmaxf(mx0, fmaxf(sc[nt][0], sc[nt][1]));
            mx1 = fmaxf(mx1, fmaxf(sc[nt][2], sc[nt][3]));
        }
        mx0 = fmaxf(mx0, __shfl_xor_sync(0xffffffffu, mx0, 1));
        mx0 = fmaxf(mx0, __shfl_xor_sync(0xffffffffu, mx0, 2));
        mx1 = fmaxf(mx1, __shfl_xor_sync(0xffffffffu, mx1, 1));
        mx1 = fmaxf(mx1, __shfl_xor_sync(0xffffffffu, mx1, 2));

        float s0 = 0.f, s1 = 0.f;
        #pragma unroll
        for (int nt = 0; nt < 8; nt++){
            sc[nt][0] = __expf(sc[nt][0] - mx0);
            sc[nt][1] = __expf(sc[nt][1] - mx0);
            sc[nt][2] = __expf(sc[nt][2] - mx1);
            sc[nt][3] = __expf(sc[nt][3] - mx1);
            s0 += sc[nt][0] + sc[nt][1];
            s1 += sc[nt][2] + sc[nt][3];
        }
        s0 += __shfl_xor_sync(0xffffffffu, s0, 1);
        s0 += __shfl_xor_sync(0xffffffffu, s0, 2);
        s1 += __shfl_xor_sync(0xffffffffu, s1, 1);
        s1 += __shfl_xor_sync(0xffffffffu, s1, 2);
        float inv0 = 1.f / s0, inv1 = 1.f / s1;

        float oc[2][4];
        oc[0][0]=oc[0][1]=oc[0][2]=oc[0][3]=0.f;
        oc[1][0]=oc[1][1]=oc[1][2]=oc[1][3]=0.f;
        #pragma unroll
        for (int ksp = 0; ksp < 4; ksp++){
            uint32_t pf[4];
            pf[0] = pack_h2(sc[2*ksp  ][0]*inv0, sc[2*ksp  ][1]*inv0);
            pf[1] = pack_h2(sc[2*ksp  ][2]*inv1, sc[2*ksp  ][3]*inv1);
            pf[2] = pack_h2(sc[2*ksp+1][0]*inv0, sc[2*ksp+1][1]*inv0);
            pf[3] = pack_h2(sc[2*ksp+1][2]*inv1, sc[2*ksp+1][3]*inv1);
            MMA_F16(oc[0], pf, vf[ksp][0], vf[ksp][1]);
            MMA_F16(oc[1], pf, vf[ksp][2], vf[ksp][3]);
        }

        int pr = l0 + (lane >> 2);
        #pragma unroll
        for (int n = 0; n < 2; n++){
            if (pr < 49)
                *(uint32_t*)(ost + pr*PH + wrp*16 + n*8 + cbase) = pack_h2(oc[n][0], oc[n][1]);
            if (pr + 8 < 49)
                *(uint32_t*)(ost + (pr+8)*PH + wrp*16 + n*8 + cbase) = pack_h2(oc[n][2], oc[n][3]);
        }
    }
    __syncthreads();   // O complete in qsm; k/v fragments dead

    // ---- load W_out (128 rows x 128 c) into ksm..vsm region ----
    #pragma unroll
    for (int i = 0; i < 8; i++){
        int idx = tid + i * 256;              // 0..2047 uint4
        int row = idx >> 4, piece = idx & 15;
        *(uint4*)(ksm + row * PH + piece * 8) = *(const uint4*)(Wout + row * 128 + piece * 8);
    }
    __syncthreads();

    // ---- proj GEMM: out[p][o] = sum_c O[p][c] * Wout[o][c] + bias[o] ----
    {
        const int pt    = wrp >> 1;           // pos-tile 0..3
        const int l0p   = pt * 16;
        const int n0    = (wrp & 1) * 64;     // out-col half
        const uint32_t wsb = ksb;             // W_out base

        uint32_t paoff = qsb + (uint32_t)((l0p + ((quad & 1) << 3) + row8) * (PH*2) + ((quad >> 1) << 4));
        uint32_t pboff[2];
        #pragma unroll
        for (int g = 0; g < 2; g++)
            pboff[g] = wsb + (uint32_t)((n0 + g*32 + (quad << 3) + row8) * (PH*2));

        float acc[8][4];
        #pragma unroll
        for (int nt = 0; nt < 8; nt++)
            #pragma unroll
            for (int q = 0; q < 4; q++) acc[nt][q] = 0.f;

        #pragma unroll
        for (int ks = 0; ks < 8; ks++){
            const uint32_t kb = ks * 32;
            uint32_t af[4], bf[2][2][4];
            LDSM_X4(af[0], af[1], af[2], af[3], paoff + kb);
            #pragma unroll
            for (int g = 0; g < 2; g++){
                LDSM_X4(bf[g][0][0], bf[g][0][1], bf[g][0][2], bf[g][0][3], pboff[g] + kb);
                LDSM_X4(bf[g][1][0], bf[g][1][1], bf[g][1][2], bf[g][1][3], pboff[g] + kb + 16);
            }
            #pragma unroll
            for (int nt = 0; nt < 8; nt++){
                int g = nt >> 2, j = nt & 3;
                MMA_F16(acc[nt], af, bf[g][0][j], bf[g][1][j]);
            }
        }

        // epilogue: final fp32 with bias, direct to output layout [b][o][pix]
        int pr1 = l0p + (lane >> 2);
        int pr2 = pr1 + 8;
        int pix1 = (prow + pr1 / 7) * 224 + pcol + (pr1 % 7);
        int pix2 = (prow + pr2 / 7) * 224 + pcol + (pr2 % 7);
        bool ok1 = (pr1 < 49), ok2 = (pr2 < 49);
        float* ob = Out + (size_t)b * 128 * HW;
        #pragma unroll
        for (int nt = 0; nt < 8; nt++){
            int o = n0 + nt*8 + ((lane & 3) << 1);
            float bv0 = bsm[o], bv1 = bsm[o+1];
            float* c0 = ob + (size_t)o * HW;
            float* c1 = c0 + HW;
            if (ok1){
                c0[pix1] = acc[nt][0] + bv0;
                c1[pix1] = acc[nt][1] + bv1;
            }
            if (ok2){
                c0[pix2] = acc[nt][2] + bv0;
                c1[pix2] = acc[nt][3] + bv1;
            }
        }
    }
}

// ---------------- launch ----------------
extern "C" void kernel_launch(void* const* d_in, const int* in_sizes, int n_in,
                              void* d_out, int out_size)
{
    const float* x     = (const float*)d_in[0];
    const float* w_qkv = (const float*)d_in[1];
    const float* b_qkv = (const float*)d_in[2];
    const float* w_out = (const float*)d_in[3];
    const float* b_out = (const float*)d_in[4];
    float* out = (float*)d_out;

    __half *qkvh, *xh, *wh;
    cudaGetSymbolAddress((void**)&qkvh, g_qkvh);
    cudaGetSymbolAddress((void**)&xh, g_xh);
    cudaGetSymbolAddress((void**)&wh, g_wh);

    cudaFuncSetAttribute(xconv,     cudaFuncAttributeMaxDynamicSharedMemorySize, XCONV_SMEM);
    cudaFuncSetAttribute(gemm_tc,   cudaFuncAttributeMaxDynamicSharedMemorySize, GEMM_SMEM);
    cudaFuncSetAttribute(attn_proj, cudaFuncAttributeMaxDynamicSharedMemorySize, ATT_SMEM);

    wconv<<<48, 256>>>(w_qkv, wh, 12288);
    wconv<<<16, 256>>>(w_out, wh + 49152, 4096);
    xconv<<<dim3(32, 2, 4), 256, XCONV_SMEM>>>(x, xh);
    gemm_tc<<<dim3(NTILE, 3, 4), 256, GEMM_SMEM>>>(wh, 0, xh, b_qkv, qkvh, 384);
    attn_proj<<<4096, 256, ATT_SMEM>>>(qkvh, wh + 49152, b_out, out);
}

// round 14
// speedup vs baseline: 1.0185x; 1.0185x over previous
#include <cuda_runtime.h>
#include <cuda_fp16.h>
#include <cstdint>

// ---------------- problem constants ----------------
#define HW    50176          // 224*224 (= 1024 windows * 49)
#define NTILE 392            // HW / 128

// scratch  (qkv padded by 64 halves for attention's aligned-span loads)
__device__ __half g_qkvh[77070400];  // [4][384][p' window-major] fp16
__device__ __half g_xh[25690112];    // x tiles [4*392][n=128 (p')][k=128] fp16
__device__ __half g_ah[25690112];    // attn-out tiles [4*392][n=128 (row-major pixel)][k=128]
__device__ __half g_wh[65536];       // w_qkv (384 rows) then w_out (128 rows), [row][128]

// ---------------- helpers ----------------
__device__ __forceinline__ uint32_t smem_u32(const void* p){
    uint32_t a;
    asm("{ .reg .u64 t; cvta.to.shared.u64 t, %1; cvt.u32.u64 %0, t; }" : "=r"(a) : "l"(p));
    return a;
}
__device__ __forceinline__ uint32_t pack_h2(float a, float b){
    __half2 h = __floats2half2_rn(a, b);
    return *(uint32_t*)&h;
}

#define LDSM_X4(r0, r1, r2, r3, addr)                                                     \
    asm volatile("ldmatrix.sync.aligned.m8n8.x4.shared.b16 {%0,%1,%2,%3}, [%4];"          \
        : "=r"(r0), "=r"(r1), "=r"(r2), "=r"(r3) : "r"(addr))

#define LDSM_X4T(r0, r1, r2, r3, addr)                                                    \
    asm volatile("ldmatrix.sync.aligned.m8n8.x4.trans.shared.b16 {%0,%1,%2,%3}, [%4];"    \
        : "=r"(r0), "=r"(r1), "=r"(r2), "=r"(r3) : "r"(addr))

#define MMA_F16(d, a, b0, b1)                                                             \
    asm volatile("mma.sync.aligned.m16n8k16.row.col.f32.f16.f16.f32 "                     \
        "{%0,%1,%2,%3}, {%4,%5,%6,%7}, {%8,%9}, {%0,%1,%2,%3};"                           \
        : "+f"((d)[0]), "+f"((d)[1]), "+f"((d)[2]), "+f"((d)[3])                          \
        : "r"((a)[0]), "r"((a)[1]), "r"((a)[2]), "r"((a)[3]), "r"(b0), "r"(b1))

#define CP16(dst, src)                                                                    \
    asm volatile("cp.async.ca.shared.global [%0], [%1], 16;" :: "r"(dst), "l"(src) : "memory")
#define CP_COMMIT  asm volatile("cp.async.commit_group;" ::: "memory")
#define CP_WAIT(n) asm volatile("cp.async.wait_group %0;" :: "n"(n) : "memory")

// =====================================================================
// weight fp32 -> fp16 (one-shot, tiny)
// =====================================================================
__global__ void wconv(const float* __restrict__ W, __half* __restrict__ Wh, int n4)
{
    int i = blockIdx.x * 256 + threadIdx.x;
    if (i >= n4) return;
    float4 v = ((const float4*)W)[i];
    *(uint2*)(Wh + i*4) = make_uint2(pack_h2(v.x, v.y), pack_h2(v.z, v.w));
}

// =====================================================================
// xconv: band-wise coalesced transpose (unchanged, proven).
// =====================================================================
#define XC_PITCH 1632
#define XCONV_SMEM (16*XC_PITCH*4)   // 104448
__global__ __launch_bounds__(256)
void xconv(const float* __restrict__ X, __half* __restrict__ Xh)
{
    extern __shared__ float ts[];
    const int tid  = threadIdx.x;
    const int band = blockIdx.x;
    const int half = blockIdx.y;
    const int b    = blockIdx.z;
    const int ch0  = half * 64;

    #pragma unroll 1
    for (int g = 0; g < 4; g++){
        if (g) __syncthreads();
        const int cbase = ch0 + g * 16;

        #pragma unroll
        for (int i = 0; i < 25; i++){
            int idx = tid + i * 256;
            if (idx < 6272){
                int c = idx / 392;
                int j = idx - c * 392;
                float4 v = *(const float4*)(X + ((size_t)(b*128 + cbase + c)) * HW + band*1568 + j*4);
                int r = j / 56;
                float* d = ts + c * XC_PITCH + j*4 + r*8;
                d[0] = v.x; d[1] = v.y; d[2] = v.z; d[3] = v.w;
            }
        }
        __syncthreads();

        for (int idx = tid; idx < 1568; idx += 256){
            int lw = idx / 49;
            int l  = idx - lw * 49;
            int r  = l / 7;
            int q  = l - r * 7;
            int pb = r*224 + lw*7 + q + r*8;
            uint32_t h[8];
            #pragma unroll
            for (int j = 0; j < 8; j++){
                float v0 = ts[(2*j  ) * XC_PITCH + pb];
                float v1 = ts[(2*j+1) * XC_PITCH + pb];
                h[j] = pack_h2(v0, v1);
            }
            int pg = (band*32 + lw) * 49 + l;
            int t = pg >> 7, n = pg & 127;
            __half* o = Xh + (((size_t)(b*NTILE + t)) * 128 + n) * 128 + cbase;
            *(uint4*)(o)     = make_uint4(h[0], h[1], h[2], h[3]);
            *(uint4*)(o + 8) = make_uint4(h[4], h[5], h[6], h[7]);
        }
    }
}

// =====================================================================
// PERSISTENT fp16 mma.sync GEMM: W tile staged once per CTA; loop over
// n-tiles with 2-stage cp.async pipeline on B (prefetch i+2 while
// computing i). Out[b][m][n] = sum_k W[m][k]*B[n][k] + bias[m].
// grid = (P, Mtiles, 4); CTA handles nt = blockIdx.x, +P, +2P, ...
// =====================================================================
#define APITCH 272                   // 128 fp16 + 16B pad
#define A_SZ   34816                 // 128 * 272
#define GEMM_SMEM (3*A_SZ)           // A + 2 B stages = 104448

__global__ __launch_bounds__(256, 2)
void gemm_persist(const __half* __restrict__ Wh, int wofs,
                  const __half* __restrict__ Bt,
                  const float* __restrict__ bias, void* __restrict__ OutV,
                  int Mtot, int fp16out, int P)
{
    extern __shared__ char sm[];
    const uint32_t sb = smem_u32(sm);
    const int tid  = threadIdx.x;
    const int wid  = tid >> 5;
    const int lane = tid & 31;
    const int m0t  = blockIdx.y * 128;
    const int b    = blockIdx.z;
    const int nt0  = blockIdx.x;

    const __half* wp = Wh + wofs + (size_t)m0t * 128;
    const __half* btb = Bt + ((size_t)(b * NTILE) << 14);

    // ---- stage A (weights) once: 2048 uint4 ----
    #pragma unroll
    for (int i = 0; i < 8; i++){
        int idx = tid + i * 256;
        int row = idx >> 4, piece = idx & 15;
        *(uint4*)(sm + row * APITCH + piece * 16) = *(const uint4*)(wp + row * 128 + piece * 8);
    }

    // ---- B prefetch helper (one commit group per tile) ----
#define PREFETCH_B(nt, stg) do {                                                          \
    const __half* bp = btb + ((size_t)(nt) << 14);                                        \
    uint32_t s0 = sb + A_SZ + (stg) * A_SZ;                                               \
    _Pragma("unroll")                                                                     \
    for (int i = 0; i < 8; i++){                                                          \
        int idx = tid + i * 256;                                                          \
        int row = idx >> 4, piece = idx & 15;                                             \
        CP16(s0 + row * APITCH + piece * 16, bp + row * 128 + piece * 8);                 \
    }                                                                                     \
    CP_COMMIT;                                                                            \
} while (0)

    PREFETCH_B(nt0, 0);
    if (nt0 + P < NTILE) PREFETCH_B(nt0 + P, 1);

    const int m0w = (wid >> 1) * 32;
    const int n0w = (wid & 1) * 64;
    const int row8 = lane & 7, quad = lane >> 3;

    uint32_t aoff[2], boff[2];
    #pragma unroll
    for (int mt = 0; mt < 2; mt++)
        aoff[mt] = sb + (uint32_t)((m0w + mt*16 + ((quad & 1) << 3) + row8) * APITCH + ((quad >> 1) << 4));
    #pragma unroll
    for (int g = 0; g < 2; g++)
        boff[g] = (uint32_t)((n0w + g*32 + (quad << 3) + row8) * APITCH);

    // bias hoisted (fixed m rows per thread)
    const int r0a = m0w + (lane >> 2);
    const int r0b = m0w + 16 + (lane >> 2);
    float bv0a = bias[m0t + r0a],     bv1a = bias[m0t + r0a + 8];
    float bv0b = bias[m0t + r0b],     bv1b = bias[m0t + r0b + 8];

    int stg = 0;
    for (int nt = nt0; nt < NTILE; nt += P){
        if (nt + P >= NTILE) { CP_WAIT(0); } else { CP_WAIT(1); }
        __syncthreads();
        const uint32_t s0 = sb + A_SZ + stg * A_SZ;

        float acc[2][8][4];
        #pragma unroll
        for (int mt = 0; mt < 2; mt++)
            #pragma unroll
            for (int ntj = 0; ntj < 8; ntj++)
                #pragma unroll
                for (int q = 0; q < 4; q++) acc[mt][ntj][q] = 0.f;

        #pragma unroll
        for (int ks = 0; ks < 8; ks++){
            const uint32_t kb = ks * 32;
            uint32_t af[2][4], bf[2][2][4];
            #pragma unroll
            for (int mt = 0; mt < 2; mt++)
                LDSM_X4(af[mt][0], af[mt][1], af[mt][2], af[mt][3], aoff[mt] + kb);
            #pragma unroll
            for (int g = 0; g < 2; g++){
                LDSM_X4(bf[g][0][0], bf[g][0][1], bf[g][0][2], bf[g][0][3], s0 + boff[g] + kb);
                LDSM_X4(bf[g][1][0], bf[g][1][1], bf[g][1][2], bf[g][1][3], s0 + boff[g] + kb + 16);
            }
            #pragma unroll
            for (int mt = 0; mt < 2; mt++)
                #pragma unroll
                for (int ntj = 0; ntj < 8; ntj++){
                    int g = ntj >> 2, j = ntj & 3;
                    MMA_F16(acc[mt][ntj], af[mt], bf[g][0][j], bf[g][1][j]);
                }
        }

        __syncthreads();                      // stage consumed
        if (nt + 2*P < NTILE) PREFETCH_B(nt + 2*P, stg);
        stg ^= 1;

        // ---- epilogue (regs only; overlaps next tile's cp.async) ----
        const int n0t = nt * 128;
        #pragma unroll
        for (int mt = 0; mt < 2; mt++){
            int r0 = (mt == 0) ? r0a : r0b;
            float bv0 = (mt == 0) ? bv0a : bv0b;
            float bv1 = (mt == 0) ? bv1a : bv1b;
            #pragma unroll
            for (int ntj = 0; ntj < 8; ntj++){
                int col = n0t + n0w + ntj*8 + ((lane & 3) << 1);
                if (fp16out){
                    __half* OutH = (__half*)OutV;
                    *(uint32_t*)(OutH + ((size_t)(b * Mtot + m0t + r0)    ) * HW + col) =
                        pack_h2(acc[mt][ntj][0] + bv0, acc[mt][ntj][1] + bv0);
                    *(uint32_t*)(OutH + ((size_t)(b * Mtot + m0t + r0 + 8)) * HW + col) =
                        pack_h2(acc[mt][ntj][2] + bv1, acc[mt][ntj][3] + bv1);
                } else {
                    float* Out = (float*)OutV;
                    *(float2*)(Out + ((size_t)(b * Mtot + m0t + r0)    ) * HW + col) =
                        make_float2(acc[mt][ntj][0] + bv0, acc[mt][ntj][1] + bv0);
                    *(float2*)(Out + ((size_t)(b * Mtot + m0t + r0 + 8)) * HW + col) =
                        make_float2(acc[mt][ntj][2] + bv1, acc[mt][ntj][3] + bv1);
                }
            }
        }
    }
#undef PREFETCH_B
}

// =====================================================================
// warp-per-head windowed attention (R11, proven): one CTA (256 thr)
// per window, warp = head. Writes fp16 tiles for the proj GEMM.
// =====================================================================
#define PH 136                     // smem pitch in halves (272B)
#define ATT_SMEM (3*64*PH*2)       // 52224

__global__ __launch_bounds__(256)
void attn_mma(const __half* __restrict__ qkv, __half* __restrict__ Ah)
{
    extern __shared__ __half asm_[];
    __half* qsm = asm_;
    __half* ksm = asm_ + 64*PH;
    __half* vsm = asm_ + 128*PH;

    const int tid  = threadIdx.x;
    const int lane = tid & 31;
    const int wrp  = tid >> 5;
    const int wi   = blockIdx.x;
    const int b    = wi >> 10;
    const int w    = wi & 1023;
    const int prow = (w >> 5) * 7, pcol = (w & 31) * 7;

    if (tid < 255){
        ((uint4*)(qsm + 49*PH))[tid] = make_uint4(0,0,0,0);
        ((uint4*)(ksm + 49*PH))[tid] = make_uint4(0,0,0,0);
        ((uint4*)(vsm + 49*PH))[tid] = make_uint4(0,0,0,0);
    }

    const int w49    = w * 49;
    const int astart = w49 & ~7;
    const int off0   = astart - w49;
    const __half* qp = qkv + (size_t)(b * 384      ) * HW;
    const __half* kp = qkv + (size_t)(b * 384 + 128) * HW;
    const __half* vp = qkv + (size_t)(b * 384 + 256) * HW;
    const __half hscale = __float2half(0.25f);

    #pragma unroll
    for (int i = 0; i < 4; i++){
        int idx = tid + i * 256;
        int c = idx >> 3, piece = idx & 7;
        int p0 = off0 + piece * 8;
        size_t ga = (size_t)c * HW + astart + piece * 8;

        uint4 vq = *(const uint4*)(qp + ga);
        __half* hq = (__half*)&vq;
        #pragma unroll
        for (int j = 0; j < 8; j++){
            int p = p0 + j;
            if ((unsigned)p < 49u) qsm[p*PH + c] = __hmul(hq[j], hscale);
        }
        uint4 vk = *(const uint4*)(kp + ga);
        __half* hk = (__half*)&vk;
        #pragma unroll
        for (int j = 0; j < 8; j++){
            int p = p0 + j;
            if ((unsigned)p < 49u) ksm[p*PH + c] = hk[j];
        }
        uint4 vv = *(const uint4*)(vp + ga);
        __half* hv = (__half*)&vv;
        #pragma unroll
        for (int j = 0; j < 8; j++){
            int p = p0 + j;
            if ((unsigned)p < 49u) vsm[p*PH + c] = hv[j];
        }
    }
    __syncthreads();

    const uint32_t qsb = smem_u32(qsm), ksb = smem_u32(ksm), vsb = smem_u32(vsm);
    const int row8 = lane & 7, quad = lane >> 3;
    const int cbase = 2 * (lane & 3);
    const uint32_t hoff = (uint32_t)wrp * 32;

    uint32_t kf[2][2][4];
    #pragma unroll
    for (int g = 0; g < 2; g++){
        uint32_t ba = ksb + (uint32_t)((g*32 + quad*8 + row8) * (PH*2)) + hoff;
        LDSM_X4(kf[g][0][0], kf[g][0][1], kf[g][0][2], kf[g][0][3], ba);
        LDSM_X4(kf[g][1][0], kf[g][1][1], kf[g][1][2], kf[g][1][3], ba + 16);
    }
    uint32_t vf[4][4];
    #pragma unroll
    for (int ksp = 0; ksp < 4; ksp++){
        uint32_t va = vsb + (uint32_t)((ksp*16 + (lane & 15)) * (PH*2)) + hoff + ((lane >> 4) << 4);
        LDSM_X4T(vf[ksp][0], vf[ksp][1], vf[ksp][2], vf[ksp][3], va);
    }

    __half* ost = qsm;

    #pragma unroll
    for (int lt = 0; lt < 4; lt++){
        const int l0 = lt * 16;
        uint32_t af[4];
        LDSM_X4(af[0], af[1], af[2], af[3],
                qsb + (uint32_t)((l0 + ((quad & 1) << 3) + row8) * (PH*2)) + hoff + ((quad >> 1) << 4));

        float sc[8][4];
        #pragma unroll
        for (int nt = 0; nt < 8; nt++){
            sc[nt][0] = sc[nt][1] = sc[nt][2] = sc[nt][3] = 0.f;
            int g = nt >> 2, j = nt & 3;
            MMA_F16(sc[nt], af, kf[g][0][j], kf[g][1][j]);
        }

        float mx0 = -1e30f, mx1 = -1e30f;
        #pragma unroll
        for (int nt = 0; nt < 8; nt++){
            int col0 = nt*8 + cbase;
            if (col0 > 48){ sc[nt][0] = -1e30f; sc[nt][2] = -1e30f; }
            if (col0 + 1 > 48){ sc[nt][1] = -1e30f; sc[nt][3] = -1e30f; }
            mx0 = fmaxf(mx0, fmaxf(sc[nt][0], sc[nt][1]));
            mx1 = fmaxf(mx1, fmaxf(sc[nt][2], sc[nt][3]));
        }
        mx0 = fmaxf(mx0, __shfl_xor_sync(0xffffffffu, mx0, 1));
        mx0 = fmaxf(mx0, __shfl_xor_sync(0xffffffffu, mx0, 2));
        mx1 = fmaxf(mx1, __shfl_xor_sync(0xffffffffu, mx1, 1));
        mx1 = fmaxf(mx1, __shfl_xor_sync(0xffffffffu, mx1, 2));

        float s0 = 0.f, s1 = 0.f;
        #pragma unroll
        for (int nt = 0; nt < 8; nt++){
            sc[nt][0] = __expf(sc[nt][0] - mx0);
            sc[nt][1] = __expf(sc[nt][1] - mx0);
            sc[nt][2] = __expf(sc[nt][2] - mx1);
            sc[nt][3] = __expf(sc[nt][3] - mx1);
            s0 += sc[nt][0] + sc[nt][1];
            s1 += sc[nt][2] + sc[nt][3];
        }
        s0 += __shfl_xor_sync(0xffffffffu, s0, 1);
        s0 += __shfl_xor_sync(0xffffffffu, s0, 2);
        s1 += __shfl_xor_sync(0xffffffffu, s1, 1);
        s1 += __shfl_xor_sync(0xffffffffu, s1, 2);
        float inv0 = 1.f / s0, inv1 = 1.f / s1;

        float oc[2][4];
        oc[0][0]=oc[0][1]=oc[0][2]=oc[0][3]=0.f;
        oc[1][0]=oc[1][1]=oc[1][2]=oc[1][3]=0.f;
        #pragma unroll
        for (int ksp = 0; ksp < 4; ksp++){
            uint32_t pf[4];
            pf[0] = pack_h2(sc[2*ksp  ][0]*inv0, sc[2*ksp  ][1]*inv0);
            pf[1] = pack_h2(sc[2*ksp  ][2]*inv1, sc[2*ksp  ][3]*inv1);
            pf[2] = pack_h2(sc[2*ksp+1][0]*inv0, sc[2*ksp+1][1]*inv0);
            pf[3] = pack_h2(sc[2*ksp+1][2]*inv1, sc[2*ksp+1][3]*inv1);
            MMA_F16(oc[0], pf, vf[ksp][0], vf[ksp][1]);
            MMA_F16(oc[1], pf, vf[ksp][2], vf[ksp][3]);
        }

        int pr = l0 + (lane >> 2);
        #pragma unroll
        for (int n = 0; n < 2; n++){
            if (pr < 49)
                *(uint32_t*)(ost + pr*PH + wrp*16 + n*8 + cbase) = pack_h2(oc[n][0], oc[n][1]);
            if (pr + 8 < 49)
                *(uint32_t*)(ost + (pr+8)*PH + wrp*16 + n*8 + cbase) = pack_h2(oc[n][2], oc[n][3]);
        }
    }
    __syncthreads();

    for (int idx = tid; idx < 784; idx += 256){
        int p = idx >> 4, ch = idx & 15;
        int pix = (prow + p / 7) * 224 + pcol + (p % 7);
        int t = pix >> 7, n = pix & 127;
        *(uint4*)(Ah + (((size_t)(b * NTILE + t)) * 128 + n) * 128 + ch*8) =
            *(const uint4*)(ost + p*PH + ch*8);
    }
}

// ---------------- launch ----------------
extern "C" void kernel_launch(void* const* d_in, const int* in_sizes, int n_in,
                              void* d_out, int out_size)
{
    const float* x     = (const float*)d_in[0];
    const float* w_qkv = (const float*)d_in[1];
    const float* b_qkv = (const float*)d_in[2];
    const float* w_out = (const float*)d_in[3];
    const float* b_out = (const float*)d_in[4];
    float* out = (float*)d_out;

    __half *qkvh, *xh, *ah, *wh;
    cudaGetSymbolAddress((void**)&qkvh, g_qkvh);
    cudaGetSymbolAddress((void**)&xh, g_xh);
    cudaGetSymbolAddress((void**)&ah, g_ah);
    cudaGetSymbolAddress((void**)&wh, g_wh);

    cudaFuncSetAttribute(xconv,        cudaFuncAttributeMaxDynamicSharedMemorySize, XCONV_SMEM);
    cudaFuncSetAttribute(gemm_persist, cudaFuncAttributeMaxDynamicSharedMemorySize, GEMM_SMEM);
    cudaFuncSetAttribute(attn_mma,     cudaFuncAttributeMaxDynamicSharedMemorySize, ATT_SMEM);

    wconv<<<48, 256>>>(w_qkv, wh, 12288);
    wconv<<<16, 256>>>(w_out, wh + 49152, 4096);
    xconv<<<dim3(32, 2, 4), 256, XCONV_SMEM>>>(x, xh);
    gemm_persist<<<dim3(74, 3, 4), 256, GEMM_SMEM>>>(wh, 0,     xh, b_qkv, qkvh, 384, 1, 74);
    attn_mma<<<4096, 256, ATT_SMEM>>>(qkvh, ah);
    gemm_persist<<<dim3(74, 1, 4), 256, GEMM_SMEM>>>(wh, 49152, ah, b_out, out, 128, 0, 74);
}

// round 15
// speedup vs baseline: 1.1250x; 1.1046x over previous
#include <cuda_runtime.h>
#include <cuda_fp16.h>
#include <cstdint>

// ---------------- problem constants ----------------
#define HW    50176          // 224*224 (= 1024 windows * 49)
#define NTILE 392            // HW / 128

// scratch
__device__ __half g_qkvh[77070336];  // [4][p' window-major][384] fp16  (pixel-major!)
__device__ __half g_xh[25690112];    // x tiles [4*392][n=128 (p')][k=128] fp16
__device__ __half g_ah[25690112];    // attn-out tiles [4*392][n=128 (row-major pixel)][k=128]
__device__ __half g_wh[65536];       // w_qkv (384 rows) then w_out (128 rows), [row][128]

// ---------------- helpers ----------------
__device__ __forceinline__ uint32_t smem_u32(const void* p){
    uint32_t a;
    asm("{ .reg .u64 t; cvta.to.shared.u64 t, %1; cvt.u32.u64 %0, t; }" : "=r"(a) : "l"(p));
    return a;
}
__device__ __forceinline__ uint32_t pack_h2(float a, float b){
    __half2 h = __floats2half2_rn(a, b);
    return *(uint32_t*)&h;
}

#define LDSM_X4(r0, r1, r2, r3, addr)                                                     \
    asm volatile("ldmatrix.sync.aligned.m8n8.x4.shared.b16 {%0,%1,%2,%3}, [%4];"          \
        : "=r"(r0), "=r"(r1), "=r"(r2), "=r"(r3) : "r"(addr))

#define LDSM_X4T(r0, r1, r2, r3, addr)                                                    \
    asm volatile("ldmatrix.sync.aligned.m8n8.x4.trans.shared.b16 {%0,%1,%2,%3}, [%4];"    \
        : "=r"(r0), "=r"(r1), "=r"(r2), "=r"(r3) : "r"(addr))

#define MMA_F16(d, a, b0, b1)                                                             \
    asm volatile("mma.sync.aligned.m16n8k16.row.col.f32.f16.f16.f32 "                     \
        "{%0,%1,%2,%3}, {%4,%5,%6,%7}, {%8,%9}, {%0,%1,%2,%3};"                           \
        : "+f"((d)[0]), "+f"((d)[1]), "+f"((d)[2]), "+f"((d)[3])                          \
        : "r"((a)[0]), "r"((a)[1]), "r"((a)[2]), "r"((a)[3]), "r"(b0), "r"(b1))

#define CP16(dst, src)                                                                    \
    asm volatile("cp.async.ca.shared.global [%0], [%1], 16;" :: "r"(dst), "l"(src) : "memory")
#define CP_COMMIT  asm volatile("cp.async.commit_group;" ::: "memory")
#define CP_WAIT(n) asm volatile("cp.async.wait_group %0;" :: "n"(n) : "memory")

// =====================================================================
// weight fp32 -> fp16 (one-shot, tiny)
// =====================================================================
__global__ void wconv(const float* __restrict__ W, __half* __restrict__ Wh, int n4)
{
    int i = blockIdx.x * 256 + threadIdx.x;
    if (i >= n4) return;
    float4 v = ((const float4*)W)[i];
    *(uint2*)(Wh + i*4) = make_uint2(pack_h2(v.x, v.y), pack_h2(v.z, v.w));
}

// =====================================================================
// xconv: band-wise coalesced transpose (unchanged, proven).
// =====================================================================
#define XC_PITCH 1632
#define XCONV_SMEM (16*XC_PITCH*4)   // 104448
__global__ __launch_bounds__(256)
void xconv(const float* __restrict__ X, __half* __restrict__ Xh)
{
    extern __shared__ float ts[];
    const int tid  = threadIdx.x;
    const int band = blockIdx.x;
    const int half = blockIdx.y;
    const int b    = blockIdx.z;
    const int ch0  = half * 64;

    #pragma unroll 1
    for (int g = 0; g < 4; g++){
        if (g) __syncthreads();
        const int cbase = ch0 + g * 16;

        #pragma unroll
        for (int i = 0; i < 25; i++){
            int idx = tid + i * 256;
            if (idx < 6272){
                int c = idx / 392;
                int j = idx - c * 392;
                float4 v = *(const float4*)(X + ((size_t)(b*128 + cbase + c)) * HW + band*1568 + j*4);
                int r = j / 56;
                float* d = ts + c * XC_PITCH + j*4 + r*8;
                d[0] = v.x; d[1] = v.y; d[2] = v.z; d[3] = v.w;
            }
        }
        __syncthreads();

        for (int idx = tid; idx < 1568; idx += 256){
            int lw = idx / 49;
            int l  = idx - lw * 49;
            int r  = l / 7;
            int q  = l - r * 7;
            int pb = r*224 + lw*7 + q + r*8;
            uint32_t h[8];
            #pragma unroll
            for (int j = 0; j < 8; j++){
                float v0 = ts[(2*j  ) * XC_PITCH + pb];
                float v1 = ts[(2*j+1) * XC_PITCH + pb];
                h[j] = pack_h2(v0, v1);
            }
            int pg = (band*32 + lw) * 49 + l;
            int t = pg >> 7, n = pg & 127;
            __half* o = Xh + (((size_t)(b*NTILE + t)) * 128 + n) * 128 + cbase;
            *(uint4*)(o)     = make_uint4(h[0], h[1], h[2], h[3]);
            *(uint4*)(o + 8) = make_uint4(h[4], h[5], h[6], h[7]);
        }
    }
}

#define CPITCH 144
#define STG_B  18432
#define STGSZ  36864
#define GEMM_SMEM (2*STGSZ)        // 73728

// =====================================================================
// QKV GEMM, ROLE-SWAPPED: A = x tile [pixel][k], B = W [outch][k].
// Output PIXEL-MAJOR: qkv[b][p'][384] fp16. Same cp.async 2-chunk
// mainloop as the proven R11 gemm; only staging pointers + epilogue differ.
// =====================================================================
__global__ __launch_bounds__(256, 2)
void gemm_qkv(const __half* __restrict__ Wh,
              const __half* __restrict__ Xt,
              const float* __restrict__ bias, __half* __restrict__ OutH)
{
    extern __shared__ char sm[];
    const uint32_t sb = smem_u32(sm);
    const int tid  = threadIdx.x;
    const int wid  = tid >> 5;
    const int lane = tid & 31;
    const int nt_blk = blockIdx.x;        // pixel tile
    const int m0t    = blockIdx.y * 128;  // out-channel tile (0,128,256)
    const int b      = blockIdx.z;

    const __half* xp = Xt + (((size_t)(b * NTILE + nt_blk)) << 14);  // A operand
    const __half* wp = Wh + (size_t)m0t * 128;                        // B operand

    #pragma unroll
    for (int ch = 0; ch < 2; ch++){
        uint32_t s0 = sb + ch * STGSZ;
        #pragma unroll
        for (int i = 0; i < 4; i++){
            int idx = tid + i * 256;
            int row = idx >> 3, piece = idx & 7;
            CP16(s0 + row * CPITCH + piece * 16, xp + row * 128 + ch * 64 + piece * 8);
        }
        #pragma unroll
        for (int i = 0; i < 4; i++){
            int idx = tid + i * 256;
            int row = idx >> 3, piece = idx & 7;
            CP16(s0 + STG_B + row * CPITCH + piece * 16, wp + row * 128 + ch * 64 + piece * 8);
        }
        CP_COMMIT;
    }

    const int m0w = (wid >> 1) * 32;      // pixel-row quadrant
    const int n0w = (wid & 1) * 64;       // out-channel half
    const int row8 = lane & 7, quad = lane >> 3;

    uint32_t aoff[2], boff[2];
    #pragma unroll
    for (int mt = 0; mt < 2; mt++)
        aoff[mt] = (uint32_t)((m0w + mt*16 + ((quad & 1) << 3) + row8) * CPITCH + ((quad >> 1) << 4));
    #pragma unroll
    for (int g = 0; g < 2; g++)
        boff[g] = (uint32_t)(STG_B + (n0w + g*32 + (quad << 3) + row8) * CPITCH);

    float acc[2][8][4];
    #pragma unroll
    for (int mt = 0; mt < 2; mt++)
        #pragma unroll
        for (int nt = 0; nt < 8; nt++)
            #pragma unroll
            for (int q = 0; q < 4; q++) acc[mt][nt][q] = 0.f;

    #pragma unroll
    for (int ch = 0; ch < 2; ch++){
        if (ch == 0) { CP_WAIT(1); } else { CP_WAIT(0); }
        __syncthreads();
        const uint32_t s0 = sb + ch * STGSZ;
        #pragma unroll
        for (int ks = 0; ks < 4; ks++){
            const uint32_t kb = ks * 32;
            uint32_t af[2][4], bf[2][2][4];
            #pragma unroll
            for (int mt = 0; mt < 2; mt++)
                LDSM_X4(af[mt][0], af[mt][1], af[mt][2], af[mt][3], s0 + aoff[mt] + kb);
            #pragma unroll
            for (int g = 0; g < 2; g++){
                LDSM_X4(bf[g][0][0], bf[g][0][1], bf[g][0][2], bf[g][0][3], s0 + boff[g] + kb);
                LDSM_X4(bf[g][1][0], bf[g][1][1], bf[g][1][2], bf[g][1][3], s0 + boff[g] + kb + 16);
            }
            #pragma unroll
            for (int mt = 0; mt < 2; mt++)
                #pragma unroll
                for (int nt = 0; nt < 8; nt++){
                    int g = nt >> 2, j = nt & 3;
                    MMA_F16(acc[mt][nt], af[mt], bf[g][0][j], bf[g][1][j]);
                }
        }
    }

    // ---- epilogue: pixel-major stores [b][p'][384] ----
    const size_t pbase = (size_t)b * HW + (size_t)nt_blk * 128;
    #pragma unroll
    for (int mt = 0; mt < 2; mt++){
        int r0 = m0w + mt*16 + (lane >> 2);          // pixel row in tile
        __half* row0 = OutH + (pbase + r0    ) * 384 + m0t;
        __half* row1 = OutH + (pbase + r0 + 8) * 384 + m0t;
        #pragma unroll
        for (int nt = 0; nt < 8; nt++){
            int col = n0w + nt*8 + ((lane & 3) << 1);
            float bv0 = bias[m0t + col];
            float bv1 = bias[m0t + col + 1];
            *(uint32_t*)(row0 + col) = pack_h2(acc[mt][nt][0] + bv0, acc[mt][nt][1] + bv1);
            *(uint32_t*)(row1 + col) = pack_h2(acc[mt][nt][2] + bv0, acc[mt][nt][3] + bv1);
        }
    }
}

// =====================================================================
// proj GEMM (R11 gemm_tc, fp32 out, unchanged / proven):
// Out[b][m][n] = sum_k W[m][k]*B[n][k] + bias[m]
// =====================================================================
__global__ __launch_bounds__(256, 2)
void gemm_tc(const __half* __restrict__ Wh, int wofs,
             const __half* __restrict__ Bt,
             const float* __restrict__ bias, float* __restrict__ Out,
             int Mtot)
{
    extern __shared__ char sm[];
    const uint32_t sb = smem_u32(sm);
    const int tid  = threadIdx.x;
    const int wid  = tid >> 5;
    const int lane = tid & 31;
    const int nt_blk = blockIdx.x;
    const int m0t    = blockIdx.y * 128;
    const int b      = blockIdx.z;

    const __half* wp = Wh + wofs + (size_t)m0t * 128;
    const __half* bp = Bt + (((size_t)(b * NTILE + nt_blk)) << 14);

    #pragma unroll
    for (int ch = 0; ch < 2; ch++){
        uint32_t s0 = sb + ch * STGSZ;
        #pragma unroll
        for (int i = 0; i < 4; i++){
            int idx = tid + i * 256;
            int row = idx >> 3, piece = idx & 7;
            CP16(s0 + row * CPITCH + piece * 16, wp + row * 128 + ch * 64 + piece * 8);
        }
        #pragma unroll
        for (int i = 0; i < 4; i++){
            int idx = tid + i * 256;
            int row = idx >> 3, piece = idx & 7;
            CP16(s0 + STG_B + row * CPITCH + piece * 16, bp + row * 128 + ch * 64 + piece * 8);
        }
        CP_COMMIT;
    }

    const int m0w = (wid >> 1) * 32;
    const int n0w = (wid & 1) * 64;
    const int row8 = lane & 7, quad = lane >> 3;

    uint32_t aoff[2], boff[2];
    #pragma unroll
    for (int mt = 0; mt < 2; mt++)
        aoff[mt] = (uint32_t)((m0w + mt*16 + ((quad & 1) << 3) + row8) * CPITCH + ((quad >> 1) << 4));
    #pragma unroll
    for (int g = 0; g < 2; g++)
        boff[g] = (uint32_t)(STG_B + (n0w + g*32 + (quad << 3) + row8) * CPITCH);

    float acc[2][8][4];
    #pragma unroll
    for (int mt = 0; mt < 2; mt++)
        #pragma unroll
        for (int nt = 0; nt < 8; nt++)
            #pragma unroll
            for (int q = 0; q < 4; q++) acc[mt][nt][q] = 0.f;

    #pragma unroll
    for (int ch = 0; ch < 2; ch++){
        if (ch == 0) { CP_WAIT(1); } else { CP_WAIT(0); }
        __syncthreads();
        const uint32_t s0 = sb + ch * STGSZ;
        #pragma unroll
        for (int ks = 0; ks < 4; ks++){
            const uint32_t kb = ks * 32;
            uint32_t af[2][4], bf[2][2][4];
            #pragma unroll
            for (int mt = 0; mt < 2; mt++)
                LDSM_X4(af[mt][0], af[mt][1], af[mt][2], af[mt][3], s0 + aoff[mt] + kb);
            #pragma unroll
            for (int g = 0; g < 2; g++){
                LDSM_X4(bf[g][0][0], bf[g][0][1], bf[g][0][2], bf[g][0][3], s0 + boff[g] + kb);
                LDSM_X4(bf[g][1][0], bf[g][1][1], bf[g][1][2], bf[g][1][3], s0 + boff[g] + kb + 16);
            }
            #pragma unroll
            for (int mt = 0; mt < 2; mt++)
                #pragma unroll
                for (int nt = 0; nt < 8; nt++){
                    int g = nt >> 2, j = nt & 3;
                    MMA_F16(acc[mt][nt], af[mt], bf[g][0][j], bf[g][1][j]);
                }
        }
    }

    const int n0t = nt_blk * 128;
    #pragma unroll
    for (int mt = 0; mt < 2; mt++){
        int r0 = m0w + mt*16 + (lane >> 2);
        float bv0 = bias[m0t + r0];
        float bv1 = bias[m0t + r0 + 8];
        #pragma unroll
        for (int nt = 0; nt < 8; nt++){
            int col = n0t + n0w + nt*8 + ((lane & 3) << 1);
            *(float2*)(Out + ((size_t)(b * Mtot + m0t + r0)    ) * HW + col) =
                make_float2(acc[mt][nt][0] + bv0, acc[mt][nt][1] + bv0);
            *(float2*)(Out + ((size_t)(b * Mtot + m0t + r0 + 8)) * HW + col) =
                make_float2(acc[mt][nt][2] + bv1, acc[mt][nt][3] + bv1);
        }
    }
}

// =====================================================================
// warp-per-head windowed attention. qkv is now PIXEL-MAJOR [b][p'][384]:
// a window = one contiguous 37.6KB block; load phase is a plain coalesced
// copy. Math/writeback identical to proven R11 kernel.
// =====================================================================
#define PH 136                     // smem pitch in halves (272B)
#define ATT_SMEM (3*64*PH*2)       // 52224

__global__ __launch_bounds__(256)
void attn_mma(const __half* __restrict__ qkv, __half* __restrict__ Ah)
{
    extern __shared__ __half asm_[];
    __half* qsm = asm_;
    __half* ksm = asm_ + 64*PH;
    __half* vsm = asm_ + 128*PH;

    const int tid  = threadIdx.x;
    const int lane = tid & 31;
    const int wrp  = tid >> 5;
    const int wi   = blockIdx.x;
    const int b    = wi >> 10;
    const int w    = wi & 1023;
    const int prow = (w >> 5) * 7, pcol = (w & 31) * 7;

    if (tid < 255){
        ((uint4*)(qsm + 49*PH))[tid] = make_uint4(0,0,0,0);
        ((uint4*)(ksm + 49*PH))[tid] = make_uint4(0,0,0,0);
        ((uint4*)(vsm + 49*PH))[tid] = make_uint4(0,0,0,0);
    }

    // ---- contiguous coalesced load: 49 rows x 384 halves = 2352 uint4 ----
    const __half* src = qkv + ((size_t)b * HW + (size_t)w * 49) * 384;
    const __half2 hs2 = __floats2half2_rn(0.25f, 0.25f);
    for (int idx = tid; idx < 2352; idx += 256){
        int p   = idx / 48;            // pixel row 0..48
        int seg = idx - p * 48;        // 48 uint4 per row
        int t3  = seg >> 4;            // 0:q 1:k 2:v
        int pc  = seg & 15;            // piece within tensor
        uint4 v = *(const uint4*)(src + (size_t)idx * 8);
        if (t3 == 0){
            __half2* h2 = (__half2*)&v;
            h2[0] = __hmul2(h2[0], hs2);
            h2[1] = __hmul2(h2[1], hs2);
            h2[2] = __hmul2(h2[2], hs2);
            h2[3] = __hmul2(h2[3], hs2);
        }
        __half* dst = (t3 == 0) ? qsm : (t3 == 1) ? ksm : vsm;
        *(uint4*)(dst + p*PH + pc*8) = v;
    }
    __syncthreads();

    const uint32_t qsb = smem_u32(qsm), ksb = smem_u32(ksm), vsb = smem_u32(vsm);
    const int row8 = lane & 7, quad = lane >> 3;
    const int cbase = 2 * (lane & 3);
    const uint32_t hoff = (uint32_t)wrp * 32;

    uint32_t kf[2][2][4];
    #pragma unroll
    for (int g = 0; g < 2; g++){
        uint32_t ba = ksb + (uint32_t)((g*32 + quad*8 + row8) * (PH*2)) + hoff;
        LDSM_X4(kf[g][0][0], kf[g][0][1], kf[g][0][2], kf[g][0][3], ba);
        LDSM_X4(kf[g][1][0], kf[g][1][1], kf[g][1][2], kf[g][1][3], ba + 16);
    }
    uint32_t vf[4][4];
    #pragma unroll
    for (int ksp = 0; ksp < 4; ksp++){
        uint32_t va = vsb + (uint32_t)((ksp*16 + (lane & 15)) * (PH*2)) + hoff + ((lane >> 4) << 4);
        LDSM_X4T(vf[ksp][0], vf[ksp][1], vf[ksp][2], vf[ksp][3], va);
    }

    __half* ost = qsm;

    #pragma unroll
    for (int lt = 0; lt < 4; lt++){
        const int l0 = lt * 16;
        uint32_t af[4];
        LDSM_X4(af[0], af[1], af[2], af[3],
                qsb + (uint32_t)((l0 + ((quad & 1) << 3) + row8) * (PH*2)) + hoff + ((quad >> 1) << 4));

        float sc[8][4];
        #pragma unroll
        for (int nt = 0; nt < 8; nt++){
            sc[nt][0] = sc[nt][1] = sc[nt][2] = sc[nt][3] = 0.f;
            int g = nt >> 2, j = nt & 3;
            MMA_F16(sc[nt], af, kf[g][0][j], kf[g][1][j]);
        }

        float mx0 = -1e30f, mx1 = -1e30f;
        #pragma unroll
        for (int nt = 0; nt < 8; nt++){
            int col0 = nt*8 + cbase;
            if (col0 > 48){ sc[nt][0] = -1e30f; sc[nt][2] = -1e30f; }
            if (col0 + 1 > 48){ sc[nt][1] = -1e30f; sc[nt][3] = -1e30f; }
            mx0 = fmaxf(mx0, fmaxf(sc[nt][0], sc[nt][1]));
            mx1 = fmaxf(mx1, fmaxf(sc[nt][2], sc[nt][3]));
        }
        mx0 = fmaxf(mx0, __shfl_xor_sync(0xffffffffu, mx0, 1));
        mx0 = fmaxf(mx0, __shfl_xor_sync(0xffffffffu, mx0, 2));
        mx1 = fmaxf(mx1, __shfl_xor_sync(0xffffffffu, mx1, 1));
        mx1 = fmaxf(mx1, __shfl_xor_sync(0xffffffffu, mx1, 2));

        float s0 = 0.f, s1 = 0.f;
        #pragma unroll
        for (int nt = 0; nt < 8; nt++){
            sc[nt][0] = __expf(sc[nt][0] - mx0);
            sc[nt][1] = __expf(sc[nt][1] - mx0);
            sc[nt][2] = __expf(sc[nt][2] - mx1);
            sc[nt][3] = __expf(sc[nt][3] - mx1);
            s0 += sc[nt][0] + sc[nt][1];
            s1 += sc[nt][2] + sc[nt][3];
        }
        s0 += __shfl_xor_sync(0xffffffffu, s0, 1);
        s0 += __shfl_xor_sync(0xffffffffu, s0, 2);
        s1 += __shfl_xor_sync(0xffffffffu, s1, 1);
        s1 += __shfl_xor_sync(0xffffffffu, s1, 2);
        float inv0 = 1.f / s0, inv1 = 1.f / s1;

        float oc[2][4];
        oc[0][0]=oc[0][1]=oc[0][2]=oc[0][3]=0.f;
        oc[1][0]=oc[1][1]=oc[1][2]=oc[1][3]=0.f;
        #pragma unroll
        for (int ksp = 0; ksp < 4; ksp++){
            uint32_t pf[4];
            pf[0] = pack_h2(sc[2*ksp  ][0]*inv0, sc[2*ksp  ][1]*inv0);
            pf[1] = pack_h2(sc[2*ksp  ][2]*inv1, sc[2*ksp  ][3]*inv1);
            pf[2] = pack_h2(sc[2*ksp+1][0]*inv0, sc[2*ksp+1][1]*inv0);
            pf[3] = pack_h2(sc[2*ksp+1][2]*inv1, sc[2*ksp+1][3]*inv1);
            MMA_F16(oc[0], pf, vf[ksp][0], vf[ksp][1]);
            MMA_F16(oc[1], pf, vf[ksp][2], vf[ksp][3]);
        }

        int pr = l0 + (lane >> 2);
        #pragma unroll
        for (int n = 0; n < 2; n++){
            if (pr < 49)
                *(uint32_t*)(ost + pr*PH + wrp*16 + n*8 + cbase) = pack_h2(oc[n][0], oc[n][1]);
            if (pr + 8 < 49)
                *(uint32_t*)(ost + (pr+8)*PH + wrp*16 + n*8 + cbase) = pack_h2(oc[n][2], oc[n][3]);
        }
    }
    __syncthreads();

    for (int idx = tid; idx < 784; idx += 256){
        int p = idx >> 4, ch = idx & 15;
        int pix = (prow + p / 7) * 224 + pcol + (p % 7);
        int t = pix >> 7, n = pix & 127;
        *(uint4*)(Ah + (((size_t)(b * NTILE + t)) * 128 + n) * 128 + ch*8) =
            *(const uint4*)(ost + p*PH + ch*8);
    }
}

// ---------------- launch ----------------
extern "C" void kernel_launch(void* const* d_in, const int* in_sizes, int n_in,
                              void* d_out, int out_size)
{
    const float* x     = (const float*)d_in[0];
    const float* w_qkv = (const float*)d_in[1];
    const float* b_qkv = (const float*)d_in[2];
    const float* w_out = (const float*)d_in[3];
    const float* b_out = (const float*)d_in[4];
    float* out = (float*)d_out;

    __half *qkvh, *xh, *ah, *wh;
    cudaGetSymbolAddress((void**)&qkvh, g_qkvh);
    cudaGetSymbolAddress((void**)&xh, g_xh);
    cudaGetSymbolAddress((void**)&ah, g_ah);
    cudaGetSymbolAddress((void**)&wh, g_wh);

    cudaFuncSetAttribute(xconv,    cudaFuncAttributeMaxDynamicSharedMemorySize, XCONV_SMEM);
    cudaFuncSetAttribute(gemm_qkv, cudaFuncAttributeMaxDynamicSharedMemorySize, GEMM_SMEM);
    cudaFuncSetAttribute(gemm_tc,  cudaFuncAttributeMaxDynamicSharedMemorySize, GEMM_SMEM);
    cudaFuncSetAttribute(attn_mma, cudaFuncAttributeMaxDynamicSharedMemorySize, ATT_SMEM);

    wconv<<<48, 256>>>(w_qkv, wh, 12288);
    wconv<<<16, 256>>>(w_out, wh + 49152, 4096);
    xconv<<<dim3(32, 2, 4), 256, XCONV_SMEM>>>(x, xh);
    gemm_qkv<<<dim3(NTILE, 3, 4), 256, GEMM_SMEM>>>(wh, xh, b_qkv, qkvh);
    attn_mma<<<4096, 256, ATT_SMEM>>>(qkvh, ah);
    gemm_tc<<<dim3(NTILE, 1, 4), 256, GEMM_SMEM>>>(wh, 49152, ah, b_out, out, 128);
}

// round 16
// speedup vs baseline: 1.1546x; 1.0263x over previous
#include <cuda_runtime.h>
#include <cuda_fp16.h>
#include <cstdint>

// ---------------- problem constants ----------------
#define HW    50176          // 224*224 (= 1024 windows * 49)
#define NTILE 392            // HW / 128

// scratch
__device__ __half g_qkvh[77070336];  // [4][p' window-major][384] fp16  (pixel-major)
__device__ __half g_xh[25690112];    // x tiles [4*392][n=128 (p')][k=128] fp16
__device__ __half g_ah[25690112];    // attn-out tiles [4*392][n=128 (row-major pixel)][k=128]
__device__ __half g_wh[65536];       // w_qkv (384 rows) then w_out (128 rows), [row][128]

// ---------------- helpers ----------------
__device__ __forceinline__ uint32_t smem_u32(const void* p){
    uint32_t a;
    asm("{ .reg .u64 t; cvta.to.shared.u64 t, %1; cvt.u32.u64 %0, t; }" : "=r"(a) : "l"(p));
    return a;
}
__device__ __forceinline__ uint32_t pack_h2(float a, float b){
    __half2 h = __floats2half2_rn(a, b);
    return *(uint32_t*)&h;
}

#define LDSM_X4(r0, r1, r2, r3, addr)                                                     \
    asm volatile("ldmatrix.sync.aligned.m8n8.x4.shared.b16 {%0,%1,%2,%3}, [%4];"          \
        : "=r"(r0), "=r"(r1), "=r"(r2), "=r"(r3) : "r"(addr))

#define LDSM_X4T(r0, r1, r2, r3, addr)                                                    \
    asm volatile("ldmatrix.sync.aligned.m8n8.x4.trans.shared.b16 {%0,%1,%2,%3}, [%4];"    \
        : "=r"(r0), "=r"(r1), "=r"(r2), "=r"(r3) : "r"(addr))

#define MMA_F16(d, a, b0, b1)                                                             \
    asm volatile("mma.sync.aligned.m16n8k16.row.col.f32.f16.f16.f32 "                     \
        "{%0,%1,%2,%3}, {%4,%5,%6,%7}, {%8,%9}, {%0,%1,%2,%3};"                           \
        : "+f"((d)[0]), "+f"((d)[1]), "+f"((d)[2]), "+f"((d)[3])                          \
        : "r"((a)[0]), "r"((a)[1]), "r"((a)[2]), "r"((a)[3]), "r"(b0), "r"(b1))

#define CP16(dst, src)                                                                    \
    asm volatile("cp.async.ca.shared.global [%0], [%1], 16;" :: "r"(dst), "l"(src) : "memory")
#define CP_COMMIT  asm volatile("cp.async.commit_group;" ::: "memory")
#define CP_WAIT(n) asm volatile("cp.async.wait_group %0;" :: "n"(n) : "memory")

// =====================================================================
// weight fp32 -> fp16 (both weight arrays, one launch)
// =====================================================================
__global__ void wconv(const float* __restrict__ Wq, const float* __restrict__ Wo,
                      __half* __restrict__ Wh)
{
    int i = blockIdx.x * 256 + threadIdx.x;       // 0..16383 float4 units
    if (i >= 16384) return;
    const float* src = (i < 12288) ? (Wq + i*4) : (Wo + (i - 12288)*4);
    float4 v = *(const float4*)src;
    *(uint2*)(Wh + i*4) = make_uint2(pack_h2(v.x, v.y), pack_h2(v.z, v.w));
}

// =====================================================================
// xconv: band-wise coalesced transpose (unchanged, proven).
// =====================================================================
#define XC_PITCH 1632
#define XCONV_SMEM (16*XC_PITCH*4)   // 104448
__global__ __launch_bounds__(256)
void xconv(const float* __restrict__ X, __half* __restrict__ Xh)
{
    extern __shared__ float ts[];
    const int tid  = threadIdx.x;
    const int band = blockIdx.x;
    const int half = blockIdx.y;
    const int b    = blockIdx.z;
    const int ch0  = half * 64;

    #pragma unroll 1
    for (int g = 0; g < 4; g++){
        if (g) __syncthreads();
        const int cbase = ch0 + g * 16;

        #pragma unroll
        for (int i = 0; i < 25; i++){
            int idx = tid + i * 256;
            if (idx < 6272){
                int c = idx / 392;
                int j = idx - c * 392;
                float4 v = *(const float4*)(X + ((size_t)(b*128 + cbase + c)) * HW + band*1568 + j*4);
                int r = j / 56;
                float* d = ts + c * XC_PITCH + j*4 + r*8;
                d[0] = v.x; d[1] = v.y; d[2] = v.z; d[3] = v.w;
            }
        }
        __syncthreads();

        for (int idx = tid; idx < 1568; idx += 256){
            int lw = idx / 49;
            int l  = idx - lw * 49;
            int r  = l / 7;
            int q  = l - r * 7;
            int pb = r*224 + lw*7 + q + r*8;
            uint32_t h[8];
            #pragma unroll
            for (int j = 0; j < 8; j++){
                float v0 = ts[(2*j  ) * XC_PITCH + pb];
                float v1 = ts[(2*j+1) * XC_PITCH + pb];
                h[j] = pack_h2(v0, v1);
            }
            int pg = (band*32 + lw) * 49 + l;
            int t = pg >> 7, n = pg & 127;
            __half* o = Xh + (((size_t)(b*NTILE + t)) * 128 + n) * 128 + cbase;
            *(uint4*)(o)     = make_uint4(h[0], h[1], h[2], h[3]);
            *(uint4*)(o + 8) = make_uint4(h[4], h[5], h[6], h[7]);
        }
    }
}

#define CPITCH 144
#define STG_B  18432
#define STGSZ  36864
#define GEMM_SMEM (2*STGSZ)        // 73728

// =====================================================================
// QKV GEMM, role-swapped (proven R15): A = x tile [pixel][k], B = W.
// Output pixel-major qkv[b][p'][384] fp16.
// =====================================================================
__global__ __launch_bounds__(256, 2)
void gemm_qkv(const __half* __restrict__ Wh,
              const __half* __restrict__ Xt,
              const float* __restrict__ bias, __half* __restrict__ OutH)
{
    extern __shared__ char sm[];
    const uint32_t sb = smem_u32(sm);
    const int tid  = threadIdx.x;
    const int wid  = tid >> 5;
    const int lane = tid & 31;
    const int nt_blk = blockIdx.x;
    const int m0t    = blockIdx.y * 128;
    const int b      = blockIdx.z;

    const __half* xp = Xt + (((size_t)(b * NTILE + nt_blk)) << 14);
    const __half* wp = Wh + (size_t)m0t * 128;

    #pragma unroll
    for (int ch = 0; ch < 2; ch++){
        uint32_t s0 = sb + ch * STGSZ;
        #pragma unroll
        for (int i = 0; i < 4; i++){
            int idx = tid + i * 256;
            int row = idx >> 3, piece = idx & 7;
            CP16(s0 + row * CPITCH + piece * 16, xp + row * 128 + ch * 64 + piece * 8);
        }
        #pragma unroll
        for (int i = 0; i < 4; i++){
            int idx = tid + i * 256;
            int row = idx >> 3, piece = idx & 7;
            CP16(s0 + STG_B + row * CPITCH + piece * 16, wp + row * 128 + ch * 64 + piece * 8);
        }
        CP_COMMIT;
    }

    const int m0w = (wid >> 1) * 32;
    const int n0w = (wid & 1) * 64;
    const int row8 = lane & 7, quad = lane >> 3;

    uint32_t aoff[2], boff[2];
    #pragma unroll
    for (int mt = 0; mt < 2; mt++)
        aoff[mt] = (uint32_t)((m0w + mt*16 + ((quad & 1) << 3) + row8) * CPITCH + ((quad >> 1) << 4));
    #pragma unroll
    for (int g = 0; g < 2; g++)
        boff[g] = (uint32_t)(STG_B + (n0w + g*32 + (quad << 3) + row8) * CPITCH);

    float acc[2][8][4];
    #pragma unroll
    for (int mt = 0; mt < 2; mt++)
        #pragma unroll
        for (int nt = 0; nt < 8; nt++)
            #pragma unroll
            for (int q = 0; q < 4; q++) acc[mt][nt][q] = 0.f;

    #pragma unroll
    for (int ch = 0; ch < 2; ch++){
        if (ch == 0) { CP_WAIT(1); } else { CP_WAIT(0); }
        __syncthreads();
        const uint32_t s0 = sb + ch * STGSZ;
        #pragma unroll
        for (int ks = 0; ks < 4; ks++){
            const uint32_t kb = ks * 32;
            uint32_t af[2][4], bf[2][2][4];
            #pragma unroll
            for (int mt = 0; mt < 2; mt++)
                LDSM_X4(af[mt][0], af[mt][1], af[mt][2], af[mt][3], s0 + aoff[mt] + kb);
            #pragma unroll
            for (int g = 0; g < 2; g++){
                LDSM_X4(bf[g][0][0], bf[g][0][1], bf[g][0][2], bf[g][0][3], s0 + boff[g] + kb);
                LDSM_X4(bf[g][1][0], bf[g][1][1], bf[g][1][2], bf[g][1][3], s0 + boff[g] + kb + 16);
            }
            #pragma unroll
            for (int mt = 0; mt < 2; mt++)
                #pragma unroll
                for (int nt = 0; nt < 8; nt++){
                    int g = nt >> 2, j = nt & 3;
                    MMA_F16(acc[mt][nt], af[mt], bf[g][0][j], bf[g][1][j]);
                }
        }
    }

    const size_t pbase = (size_t)b * HW + (size_t)nt_blk * 128;
    #pragma unroll
    for (int mt = 0; mt < 2; mt++){
        int r0 = m0w + mt*16 + (lane >> 2);
        __half* row0 = OutH + (pbase + r0    ) * 384 + m0t;
        __half* row1 = OutH + (pbase + r0 + 8) * 384 + m0t;
        #pragma unroll
        for (int nt = 0; nt < 8; nt++){
            int col = n0w + nt*8 + ((lane & 3) << 1);
            float bv0 = bias[m0t + col];
            float bv1 = bias[m0t + col + 1];
            *(uint32_t*)(row0 + col) = pack_h2(acc[mt][nt][0] + bv0, acc[mt][nt][1] + bv1);
            *(uint32_t*)(row1 + col) = pack_h2(acc[mt][nt][2] + bv0, acc[mt][nt][3] + bv1);
        }
    }
}

// =====================================================================
// proj GEMM (R11 gemm_tc, fp32 out, unchanged / proven).
// =====================================================================
__global__ __launch_bounds__(256, 2)
void gemm_tc(const __half* __restrict__ Wh, int wofs,
             const __half* __restrict__ Bt,
             const float* __restrict__ bias, float* __restrict__ Out,
             int Mtot)
{
    extern __shared__ char sm[];
    const uint32_t sb = smem_u32(sm);
    const int tid  = threadIdx.x;
    const int wid  = tid >> 5;
    const int lane = tid & 31;
    const int nt_blk = blockIdx.x;
    const int m0t    = blockIdx.y * 128;
    const int b      = blockIdx.z;

    const __half* wp = Wh + wofs + (size_t)m0t * 128;
    const __half* bp = Bt + (((size_t)(b * NTILE + nt_blk)) << 14);

    #pragma unroll
    for (int ch = 0; ch < 2; ch++){
        uint32_t s0 = sb + ch * STGSZ;
        #pragma unroll
        for (int i = 0; i < 4; i++){
            int idx = tid + i * 256;
            int row = idx >> 3, piece = idx & 7;
            CP16(s0 + row * CPITCH + piece * 16, wp + row * 128 + ch * 64 + piece * 8);
        }
        #pragma unroll
        for (int i = 0; i < 4; i++){
            int idx = tid + i * 256;
            int row = idx >> 3, piece = idx & 7;
            CP16(s0 + STG_B + row * CPITCH + piece * 16, bp + row * 128 + ch * 64 + piece * 8);
        }
        CP_COMMIT;
    }

    const int m0w = (wid >> 1) * 32;
    const int n0w = (wid & 1) * 64;
    const int row8 = lane & 7, quad = lane >> 3;

    uint32_t aoff[2], boff[2];
    #pragma unroll
    for (int mt = 0; mt < 2; mt++)
        aoff[mt] = (uint32_t)((m0w + mt*16 + ((quad & 1) << 3) + row8) * CPITCH + ((quad >> 1) << 4));
    #pragma unroll
    for (int g = 0; g < 2; g++)
        boff[g] = (uint32_t)(STG_B + (n0w + g*32 + (quad << 3) + row8) * CPITCH);

    float acc[2][8][4];
    #pragma unroll
    for (int mt = 0; mt < 2; mt++)
        #pragma unroll
        for (int nt = 0; nt < 8; nt++)
            #pragma unroll
            for (int q = 0; q < 4; q++) acc[mt][nt][q] = 0.f;

    #pragma unroll
    for (int ch = 0; ch < 2; ch++){
        if (ch == 0) { CP_WAIT(1); } else { CP_WAIT(0); }
        __syncthreads();
        const uint32_t s0 = sb + ch * STGSZ;
        #pragma unroll
        for (int ks = 0; ks < 4; ks++){
            const uint32_t kb = ks * 32;
            uint32_t af[2][4], bf[2][2][4];
            #pragma unroll
            for (int mt = 0; mt < 2; mt++)
                LDSM_X4(af[mt][0], af[mt][1], af[mt][2], af[mt][3], s0 + aoff[mt] + kb);
            #pragma unroll
            for (int g = 0; g < 2; g++){
                LDSM_X4(bf[g][0][0], bf[g][0][1], bf[g][0][2], bf[g][0][3], s0 + boff[g] + kb);
                LDSM_X4(bf[g][1][0], bf[g][1][1], bf[g][1][2], bf[g][1][3], s0 + boff[g] + kb + 16);
            }
            #pragma unroll
            for (int mt = 0; mt < 2; mt++)
                #pragma unroll
                for (int nt = 0; nt < 8; nt++){
                    int g = nt >> 2, j = nt & 3;
                    MMA_F16(acc[mt][nt], af[mt], bf[g][0][j], bf[g][1][j]);
                }
        }
    }

    const int n0t = nt_blk * 128;
    #pragma unroll
    for (int mt = 0; mt < 2; mt++){
        int r0 = m0w + mt*16 + (lane >> 2);
        float bv0 = bias[m0t + r0];
        float bv1 = bias[m0t + r0 + 8];
        #pragma unroll
        for (int nt = 0; nt < 8; nt++){
            int col = n0t + n0w + nt*8 + ((lane & 3) << 1);
            *(float2*)(Out + ((size_t)(b * Mtot + m0t + r0)    ) * HW + col) =
                make_float2(acc[mt][nt][0] + bv0, acc[mt][nt][1] + bv0);
            *(float2*)(Out + ((size_t)(b * Mtot + m0t + r0 + 8)) * HW + col) =
                make_float2(acc[mt][nt][2] + bv1, acc[mt][nt][3] + bv1);
        }
    }
}

// =====================================================================
// warp-per-head windowed attention, pixel-major input.
// This round: exp2 folding (log2e baked into Q scale) + late softmax
// normalization (scale O accumulators, not P fragments).
// =====================================================================
#define PH 136                     // smem pitch in halves (272B)
#define ATT_SMEM (3*64*PH*2)       // 52224

__global__ __launch_bounds__(256)
void attn_mma(const __half* __restrict__ qkv, __half* __restrict__ Ah)
{
    extern __shared__ __half asm_[];
    __half* qsm = asm_;
    __half* ksm = asm_ + 64*PH;
    __half* vsm = asm_ + 128*PH;

    const int tid  = threadIdx.x;
    const int lane = tid & 31;
    const int wrp  = tid >> 5;
    const int wi   = blockIdx.x;
    const int b    = wi >> 10;
    const int w    = wi & 1023;
    const int prow = (w >> 5) * 7, pcol = (w & 31) * 7;

    if (tid < 255){
        ((uint4*)(qsm + 49*PH))[tid] = make_uint4(0,0,0,0);
        ((uint4*)(ksm + 49*PH))[tid] = make_uint4(0,0,0,0);
        ((uint4*)(vsm + 49*PH))[tid] = make_uint4(0,0,0,0);
    }

    // ---- contiguous coalesced load: 49 rows x 384 halves = 2352 uint4 ----
    // Q scale folds softmax base-2 conversion: 0.25 * log2(e)
    const __half* src = qkv + ((size_t)b * HW + (size_t)w * 49) * 384;
    const __half2 hs2 = __floats2half2_rn(0.360673760222241f, 0.360673760222241f);
    for (int idx = tid; idx < 2352; idx += 256){
        int p   = idx / 48;
        int seg = idx - p * 48;
        int t3  = seg >> 4;
        int pc  = seg & 15;
        uint4 v = *(const uint4*)(src + (size_t)idx * 8);
        if (t3 == 0){
            __half2* h2 = (__half2*)&v;
            h2[0] = __hmul2(h2[0], hs2);
            h2[1] = __hmul2(h2[1], hs2);
            h2[2] = __hmul2(h2[2], hs2);
            h2[3] = __hmul2(h2[3], hs2);
        }
        __half* dst = (t3 == 0) ? qsm : (t3 == 1) ? ksm : vsm;
        *(uint4*)(dst + p*PH + pc*8) = v;
    }
    __syncthreads();

    const uint32_t qsb = smem_u32(qsm), ksb = smem_u32(ksm), vsb = smem_u32(vsm);
    const int row8 = lane & 7, quad = lane >> 3;
    const int cbase = 2 * (lane & 3);
    const uint32_t hoff = (uint32_t)wrp * 32;

    uint32_t kf[2][2][4];
    #pragma unroll
    for (int g = 0; g < 2; g++){
        uint32_t ba = ksb + (uint32_t)((g*32 + quad*8 + row8) * (PH*2)) + hoff;
        LDSM_X4(kf[g][0][0], kf[g][0][1], kf[g][0][2], kf[g][0][3], ba);
        LDSM_X4(kf[g][1][0], kf[g][1][1], kf[g][1][2], kf[g][1][3], ba + 16);
    }
    uint32_t vf[4][4];
    #pragma unroll
    for (int ksp = 0; ksp < 4; ksp++){
        uint32_t va = vsb + (uint32_t)((ksp*16 + (lane & 15)) * (PH*2)) + hoff + ((lane >> 4) << 4);
        LDSM_X4T(vf[ksp][0], vf[ksp][1], vf[ksp][2], vf[ksp][3], va);
    }

    __half* ost = qsm;

    #pragma unroll
    for (int lt = 0; lt < 4; lt++){
        const int l0 = lt * 16;
        uint32_t af[4];
        LDSM_X4(af[0], af[1], af[2], af[3],
                qsb + (uint32_t)((l0 + ((quad & 1) << 3) + row8) * (PH*2)) + hoff + ((quad >> 1) << 4));

        float sc[8][4];
        #pragma unroll
        for (int nt = 0; nt < 8; nt++){
            sc[nt][0] = sc[nt][1] = sc[nt][2] = sc[nt][3] = 0.f;
            int g = nt >> 2, j = nt & 3;
            MMA_F16(sc[nt], af, kf[g][0][j], kf[g][1][j]);
        }

        float mx0 = -1e30f, mx1 = -1e30f;
        #pragma unroll
        for (int nt = 0; nt < 8; nt++){
            int col0 = nt*8 + cbase;
            if (col0 > 48){ sc[nt][0] = -1e30f; sc[nt][2] = -1e30f; }
            if (col0 + 1 > 48){ sc[nt][1] = -1e30f; sc[nt][3] = -1e30f; }
            mx0 = fmaxf(mx0, fmaxf(sc[nt][0], sc[nt][1]));
            mx1 = fmaxf(mx1, fmaxf(sc[nt][2], sc[nt][3]));
        }
        mx0 = fmaxf(mx0, __shfl_xor_sync(0xffffffffu, mx0, 1));
        mx0 = fmaxf(mx0, __shfl_xor_sync(0xffffffffu, mx0, 2));
        mx1 = fmaxf(mx1, __shfl_xor_sync(0xffffffffu, mx1, 1));
        mx1 = fmaxf(mx1, __shfl_xor_sync(0xffffffffu, mx1, 2));

        float s0 = 0.f, s1 = 0.f;
        #pragma unroll
        for (int nt = 0; nt < 8; nt++){
            sc[nt][0] = exp2f(sc[nt][0] - mx0);
            sc[nt][1] = exp2f(sc[nt][1] - mx0);
            sc[nt][2] = exp2f(sc[nt][2] - mx1);
            sc[nt][3] = exp2f(sc[nt][3] - mx1);
            s0 += sc[nt][0] + sc[nt][1];
            s1 += sc[nt][2] + sc[nt][3];
        }
        s0 += __shfl_xor_sync(0xffffffffu, s0, 1);
        s0 += __shfl_xor_sync(0xffffffffu, s0, 2);
        s1 += __shfl_xor_sync(0xffffffffu, s1, 1);
        s1 += __shfl_xor_sync(0xffffffffu, s1, 2);
        float inv0 = 1.f / s0, inv1 = 1.f / s1;

        // O = P_hat . V  (unnormalized P; normalize output instead)
        float oc[2][4];
        oc[0][0]=oc[0][1]=oc[0][2]=oc[0][3]=0.f;
        oc[1][0]=oc[1][1]=oc[1][2]=oc[1][3]=0.f;
        #pragma unroll
        for (int ksp = 0; ksp < 4; ksp++){
            uint32_t pf[4];
            pf[0] = pack_h2(sc[2*ksp  ][0], sc[2*ksp  ][1]);
            pf[1] = pack_h2(sc[2*ksp  ][2], sc[2*ksp  ][3]);
            pf[2] = pack_h2(sc[2*ksp+1][0], sc[2*ksp+1][1]);
            pf[3] = pack_h2(sc[2*ksp+1][2], sc[2*ksp+1][3]);
            MMA_F16(oc[0], pf, vf[ksp][0], vf[ksp][1]);
            MMA_F16(oc[1], pf, vf[ksp][2], vf[ksp][3]);
        }

        int pr = l0 + (lane >> 2);
        #pragma unroll
        for (int n = 0; n < 2; n++){
            if (pr < 49)
                *(uint32_t*)(ost + pr*PH + wrp*16 + n*8 + cbase) = pack_h2(oc[n][0]*inv0, oc[n][1]*inv0);
            if (pr + 8 < 49)
                *(uint32_t*)(ost + (pr+8)*PH + wrp*16 + n*8 + cbase) = pack_h2(oc[n][2]*inv1, oc[n][3]*inv1);
        }
    }
    __syncthreads();

    for (int idx = tid; idx < 784; idx += 256){
        int p = idx >> 4, ch = idx & 15;
        int pix = (prow + p / 7) * 224 + pcol + (p % 7);
        int t = pix >> 7, n = pix & 127;
        *(uint4*)(Ah + (((size_t)(b * NTILE + t)) * 128 + n) * 128 + ch*8) =
            *(const uint4*)(ost + p*PH + ch*8);
    }
}

// ---------------- launch ----------------
extern "C" void kernel_launch(void* const* d_in, const int* in_sizes, int n_in,
                              void* d_out, int out_size)
{
    const float* x     = (const float*)d_in[0];
    const float* w_qkv = (const float*)d_in[1];
    const float* b_qkv = (const float*)d_in[2];
    const float* w_out = (const float*)d_in[3];
    const float* b_out = (const float*)d_in[4];
    float* out = (float*)d_out;

    __half *qkvh, *xh, *ah, *wh;
    cudaGetSymbolAddress((void**)&qkvh, g_qkvh);
    cudaGetSymbolAddress((void**)&xh, g_xh);
    cudaGetSymbolAddress((void**)&ah, g_ah);
    cudaGetSymbolAddress((void**)&wh, g_wh);

    cudaFuncSetAttribute(xconv,    cudaFuncAttributeMaxDynamicSharedMemorySize, XCONV_SMEM);
    cudaFuncSetAttribute(gemm_qkv, cudaFuncAttributeMaxDynamicSharedMemorySize, GEMM_SMEM);
    cudaFuncSetAttribute(gemm_tc,  cudaFuncAttributeMaxDynamicSharedMemorySize, GEMM_SMEM);
    cudaFuncSetAttribute(attn_mma, cudaFuncAttributeMaxDynamicSharedMemorySize, ATT_SMEM);

    wconv<<<64, 256>>>(w_qkv, w_out, wh);
    xconv<<<dim3(32, 2, 4), 256, XCONV_SMEM>>>(x, xh);
    gemm_qkv<<<dim3(NTILE, 3, 4), 256, GEMM_SMEM>>>(wh, xh, b_qkv, qkvh);
    attn_mma<<<4096, 256, ATT_SMEM>>>(qkvh, ah);
    gemm_tc<<<dim3(NTILE, 1, 4), 256, GEMM_SMEM>>>(wh, 49152, ah, b_out, out, 128);
}